// round 3
// baseline (speedup 1.0000x reference)
#include <cuda_runtime.h>

#define NTOK 4096
#define CDIM 256
#define NH   8
#define HD   32
#define SCALE 0.17677669529663687f   // 1/sqrt(32)

#define BQ 128
#define BK 64

// scratch (device globals: no allocation allowed)
__device__ float g_Qt[NH*HD*NTOK];   // Q transposed per head: [h][d][n], pre-scaled
__device__ float g_Kt[NH*HD*NTOK];   // K transposed per head: [h][d][n]
__device__ float g_V [NH*NTOK*HD];   // V: [h][n][d]
__device__ float g_T [NTOK*CDIM];    // attention output tokens [n][c]

// ---------------------------------------------------------------------------
// Kernel 1: QKV = tok @ qkv_w^T ; tok[n][c] = x[c][n]
// C[n][o] = sum_c x[c*4096+n] * w[o*256+c],  o -> (t, h, d)
// ---------------------------------------------------------------------------
__global__ __launch_bounds__(256) void qkv_kernel(const float* __restrict__ x,
                                                  const float* __restrict__ w) {
    __shared__ float As[16][64];   // [k][n-local]
    __shared__ float Bs[16][68];   // [k][o-local], padded
    const int n0 = blockIdx.x * 64;
    const int o0 = blockIdx.y * 64;
    const int tid = threadIdx.x;
    const int tx = tid & 15, ty = tid >> 4;

    float acc[4][4] = {};
    const int li = tid & 63, lk = tid >> 6;        // A-load mapping
    const int bj = tid >> 2, bk4 = (tid & 3) * 4;  // B-load mapping

    for (int c0 = 0; c0 < 256; c0 += 16) {
        #pragma unroll
        for (int kk = 0; kk < 4; kk++)
            As[lk + kk*4][li] = x[(c0 + lk + kk*4) * NTOK + n0 + li];
        float4 wb = *(const float4*)(w + (o0 + bj) * 256 + c0 + bk4);
        Bs[bk4+0][bj] = wb.x; Bs[bk4+1][bj] = wb.y;
        Bs[bk4+2][bj] = wb.z; Bs[bk4+3][bj] = wb.w;
        __syncthreads();
        #pragma unroll
        for (int k = 0; k < 16; k++) {
            float4 a = *(const float4*)(&As[k][ty*4]);
            float4 b = *(const float4*)(&Bs[k][tx*4]);
            float av[4] = {a.x,a.y,a.z,a.w};
            float bv[4] = {b.x,b.y,b.z,b.w};
            #pragma unroll
            for (int u = 0; u < 4; u++)
                #pragma unroll
                for (int v = 0; v < 4; v++)
                    acc[u][v] = fmaf(av[u], bv[v], acc[u][v]);
        }
        __syncthreads();
    }

    #pragma unroll
    for (int u = 0; u < 4; u++) {
        const int n = n0 + ty*4 + u;
        #pragma unroll
        for (int v = 0; v < 4; v++) {
            const int o = o0 + tx*4 + v;
            const int t = o >> 8, h = (o >> 5) & 7, d = o & 31;
            const float val = acc[u][v];
            if (t == 0)      g_Qt[(h*HD + d)*NTOK + n] = val * SCALE;
            else if (t == 1) g_Kt[(h*HD + d)*NTOK + n] = val;
            else             g_V [(h*NTOK + n)*HD + d] = val;
        }
    }
}

// ---------------------------------------------------------------------------
// Kernel 2: masked flash attention. One block = (128 queries, 1 head).
// Mask: dist^2(coord(n),coord(m)) <= 99 (exact integer form of dist < 10).
// z is constant within any 64/128-aligned index range -> tile-level skipping.
// ---------------------------------------------------------------------------
#define PS_STRIDE 66
#define VS_STRIDE 36
// smem floats: Qt 32*128 + Kt 32*64 + Vs 64*36 + Ps 128*66 + alpha 128 + l 128
#define ATTN_SMEM_FLOATS (32*128 + 32*64 + 64*VS_STRIDE + 128*PS_STRIDE + 256)

__global__ __launch_bounds__(256, 2) void attn_kernel() {
    extern __shared__ float sm[];
    float* Qt  = sm;                       // [k][r]   32 x 128
    float* Kt  = Qt + 32*128;              // [k][c]   32 x 64
    float* Vs  = Kt + 32*64;               // [m][d]   64 x 36(pad)
    float* Ps  = Vs + 64*VS_STRIDE;        // [r][m]  128 x 66(pad)
    float* alp = Ps + 128*PS_STRIDE;       // [128]
    float* lro = alp + 128;                // [128]

    const int tid = threadIdx.x;
    const int h  = blockIdx.y;
    const int n0 = blockIdx.x * BQ;
    const int zq  = n0 >> 8;
    const int y0q = (n0 >> 4) & 15;

    // score-phase mapping: 16x16 thread grid, each 8 rows x 4 cols
    const int tx = tid & 15, ty = tid >> 4;
    const int r0 = ty * 8, c0 = tx * 4;
    // AV-phase mapping: 32x8 grid, each 4 rows x 4 dims
    const int rg = tid >> 3, cg = tid & 7;
    const int ra = rg * 4, d0 = cg * 4;

    const float* gq = g_Qt + h*HD*NTOK;
    const float* gk = g_Kt + h*HD*NTOK;
    const float* gv = g_V  + h*NTOK*HD;

    // load Q tile (coalesced: contiguous in n)
    for (int idx = tid; idx < 32*128; idx += 256) {
        const int k = idx >> 7, r = idx & 127;
        Qt[idx] = gq[k*NTOK + n0 + r];
    }

    float mreg[8], lreg[8];
    #pragma unroll
    for (int u = 0; u < 8; u++) { mreg[u] = -1e30f; lreg[u] = 0.f; }
    float O[4][4] = {};

    int yq[8], xq[8];
    #pragma unroll
    for (int u = 0; u < 8; u++) {
        const int nq = n0 + r0 + u;
        yq[u] = (nq >> 4) & 15;
        xq[u] = nq & 15;
    }

    const int zlo = max(0, zq - 9), zhi = min(15, zq + 9);
    __syncthreads();

    for (int m0 = zlo*256; m0 <= zhi*256 + 192; m0 += BK) {
        const int zk = m0 >> 8;
        const int dz = zq - zk;
        const int y0k = (m0 >> 4) & 15;
        const int gap = max(0, max(y0k - (y0q + 7), y0q - (y0k + 3)));
        if (dz*dz + gap*gap > 99) continue;   // whole tile masked

        // load K^T tile and V tile (coalesced)
        for (int idx = tid; idx < 32*64; idx += 256)
            Kt[idx] = gk[(idx >> 6)*NTOK + m0 + (idx & 63)];
        for (int idx = tid; idx < 64*32; idx += 256) {
            const int m = idx >> 5, d = idx & 31;
            Vs[m*VS_STRIDE + d] = gv[(m0 + m)*HD + d];
        }
        __syncthreads();

        // ---- scores S = Q K^T (Q pre-scaled) ----
        float acc[8][4] = {};
        #pragma unroll 8
        for (int k = 0; k < 32; k++) {
            float4 qa = *(const float4*)(Qt + k*128 + r0);
            float4 qb = *(const float4*)(Qt + k*128 + r0 + 4);
            float4 kv = *(const float4*)(Kt + k*64  + c0);
            float qv[8] = {qa.x,qa.y,qa.z,qa.w,qb.x,qb.y,qb.z,qb.w};
            float kk[4] = {kv.x,kv.y,kv.z,kv.w};
            #pragma unroll
            for (int u = 0; u < 8; u++)
                #pragma unroll
                for (int v = 0; v < 4; v++)
                    acc[u][v] = fmaf(qv[u], kk[v], acc[u][v]);
        }

        // ---- mask + online softmax ----
        const int thr = 99 - dz*dz;
        int yk[4], xk[4];
        #pragma unroll
        for (int v = 0; v < 4; v++) {
            const int mk = m0 + c0 + v;
            yk[v] = (mk >> 4) & 15;
            xk[v] = mk & 15;
        }
        #pragma unroll
        for (int u = 0; u < 8; u++) {
            float tmax = -1e30f;
            #pragma unroll
            for (int v = 0; v < 4; v++) {
                const int dy = yq[u] - yk[v];
                const int dx = xq[u] - xk[v];
                if (dy*dy + dx*dx > thr) acc[u][v] = -1e30f;
                tmax = fmaxf(tmax, acc[u][v]);
            }
            #pragma unroll
            for (int off = 8; off; off >>= 1)
                tmax = fmaxf(tmax, __shfl_xor_sync(0xffffffffu, tmax, off));
            const float mnew = fmaxf(mreg[u], tmax);
            const float a = __expf(mreg[u] - mnew);
            float psum = 0.f;
            #pragma unroll
            for (int v = 0; v < 4; v++) {
                // guard: masked (-1e30) rows must give p==0 even if mnew==-1e30
                const float p = (acc[u][v] < -1e29f) ? 0.f : __expf(acc[u][v] - mnew);
                Ps[(r0+u)*PS_STRIDE + c0 + v] = p;
                psum += p;
            }
            #pragma unroll
            for (int off = 8; off; off >>= 1)
                psum += __shfl_xor_sync(0xffffffffu, psum, off);
            lreg[u] = lreg[u]*a + psum;
            mreg[u] = mnew;
            if (tx == 0) alp[r0+u] = a;
        }
        __syncthreads();

        // ---- O = alpha*O + P V ----
        #pragma unroll
        for (int u = 0; u < 4; u++) {
            const float a = alp[ra + u];
            #pragma unroll
            for (int v = 0; v < 4; v++) O[u][v] *= a;
        }
        #pragma unroll 4
        for (int m = 0; m < BK; m++) {
            float4 vv = *(const float4*)(Vs + m*VS_STRIDE + d0);
            float vvv[4] = {vv.x,vv.y,vv.z,vv.w};
            #pragma unroll
            for (int u = 0; u < 4; u++) {
                const float p = Ps[(ra+u)*PS_STRIDE + m];
                #pragma unroll
                for (int v = 0; v < 4; v++)
                    O[u][v] = fmaf(p, vvv[v], O[u][v]);
            }
        }
        __syncthreads();
    }

    if (tx == 0) {
        #pragma unroll
        for (int u = 0; u < 8; u++) lro[r0+u] = lreg[u];
    }
    __syncthreads();

    #pragma unroll
    for (int u = 0; u < 4; u++) {
        const float inv = 1.0f / lro[ra + u];
        float4 res;
        res.x = O[u][0]*inv; res.y = O[u][1]*inv;
        res.z = O[u][2]*inv; res.w = O[u][3]*inv;
        *(float4*)(g_T + (n0 + ra + u)*CDIM + h*HD + d0) = res;
    }
}

// ---------------------------------------------------------------------------
// Kernel 3: out[o][n] = sum_c T[n][c] * proj_w[o][c] + b[o]   (output is [C,N])
// ---------------------------------------------------------------------------
__global__ __launch_bounds__(256) void proj_kernel(const float* __restrict__ w,
                                                   const float* __restrict__ bias,
                                                   float* __restrict__ out) {
    __shared__ float Ws[16][68];   // [k][o-local]
    __shared__ float Ts[16][68];   // [k][n-local]
    const int n0 = blockIdx.x * 64;
    const int o0 = blockIdx.y * 64;
    const int tid = threadIdx.x;
    const int tx = tid & 15, ty = tid >> 4;

    float acc[4][4] = {};
    const int j = tid >> 2, k4 = (tid & 3) * 4;

    for (int c0 = 0; c0 < 256; c0 += 16) {
        float4 wv = *(const float4*)(w   + (o0 + j)*256 + c0 + k4);
        Ws[k4+0][j]=wv.x; Ws[k4+1][j]=wv.y; Ws[k4+2][j]=wv.z; Ws[k4+3][j]=wv.w;
        float4 tv = *(const float4*)(g_T + (n0 + j)*256 + c0 + k4);
        Ts[k4+0][j]=tv.x; Ts[k4+1][j]=tv.y; Ts[k4+2][j]=tv.z; Ts[k4+3][j]=tv.w;
        __syncthreads();
        #pragma unroll
        for (int k = 0; k < 16; k++) {
            float4 a = *(const float4*)(&Ws[k][ty*4]);
            float4 b = *(const float4*)(&Ts[k][tx*4]);
            float av[4] = {a.x,a.y,a.z,a.w};
            float bv[4] = {b.x,b.y,b.z,b.w};
            #pragma unroll
            for (int u = 0; u < 4; u++)
                #pragma unroll
                for (int v = 0; v < 4; v++)
                    acc[u][v] = fmaf(av[u], bv[v], acc[u][v]);
        }
        __syncthreads();
    }

    #pragma unroll
    for (int u = 0; u < 4; u++) {
        const int o = o0 + ty*4 + u;
        const float bo = bias[o];
        float4 r;
        r.x = acc[u][0] + bo; r.y = acc[u][1] + bo;
        r.z = acc[u][2] + bo; r.w = acc[u][3] + bo;
        *(float4*)(out + (size_t)o*NTOK + n0 + tx*4) = r;
    }
}

// ---------------------------------------------------------------------------
extern "C" void kernel_launch(void* const* d_in, const int* in_sizes, int n_in,
                              void* d_out, int out_size) {
    const float *x = nullptr, *wq = nullptr, *wp = nullptr, *bp = nullptr;
    for (int i = 0; i < n_in; i++) {
        switch (in_sizes[i]) {
            case 1048576: x  = (const float*)d_in[i]; break;  // x [1,256,16,16,16]
            case 196608:  wq = (const float*)d_in[i]; break;  // qkv_w [768,256]
            case 65536:   wp = (const float*)d_in[i]; break;  // proj_w [256,256]
            case 256:     bp = (const float*)d_in[i]; break;  // proj_b [256]
        }
    }
    float* out = (float*)d_out;

    cudaFuncSetAttribute(attn_kernel, cudaFuncAttributeMaxDynamicSharedMemorySize,
                         ATTN_SMEM_FLOATS * (int)sizeof(float));

    qkv_kernel <<<dim3(NTOK/64, 768/64), 256>>>(x, wq);
    attn_kernel<<<dim3(NTOK/BQ, NH), 256, ATTN_SMEM_FLOATS * (int)sizeof(float)>>>();
    proj_kernel<<<dim3(NTOK/64, CDIM/64), 256>>>(wp, bp, out);
}